// round 7
// baseline (speedup 1.0000x reference)
#include <cuda_runtime.h>
#include <cuda_bf16.h>
#include <cstdint>

#define N_ROWS   2048
#define DIM_D    512
#define DIM_H    512
#define N_HEADS  16
#define MAXM     512

// ---------------- portable PTX helpers (sm_80-level only) --------------------
__device__ __forceinline__ uint32_t smem_to_u32(const void* p) {
    uint32_t a;
    asm("{ .reg .u64 t; cvta.to.shared.u64 t, %1; cvt.u32.u64 %0, t; }" : "=r"(a) : "l"(p));
    return a;
}
__device__ __forceinline__ void cp_async16(uint32_t dst, const void* src, int src_bytes) {
    asm volatile("cp.async.cg.shared.global [%0], [%1], 16, %2;"
                 :: "r"(dst), "l"(src), "r"(src_bytes) : "memory");
}
#define CP_COMMIT() asm volatile("cp.async.commit_group;" ::: "memory")
#define CP_WAIT(n)  asm volatile("cp.async.wait_group %0;" :: "n"(n) : "memory")

__device__ __forceinline__ void ldsm_x4(uint32_t* r, uint32_t addr) {
    asm volatile("ldmatrix.sync.aligned.m8n8.x4.shared.b16 {%0,%1,%2,%3}, [%4];"
                 : "=r"(r[0]), "=r"(r[1]), "=r"(r[2]), "=r"(r[3]) : "r"(addr));
}
__device__ __forceinline__ void mma16816(float* d, const uint32_t* a, uint32_t b0, uint32_t b1) {
    asm volatile("mma.sync.aligned.m16n8k16.row.col.f32.bf16.bf16.f32 "
                 "{%0,%1,%2,%3}, {%4,%5,%6,%7}, {%8,%9}, {%0,%1,%2,%3};"
                 : "+f"(d[0]), "+f"(d[1]), "+f"(d[2]), "+f"(d[3])
                 : "r"(a[0]), "r"(a[1]), "r"(a[2]), "r"(a[3]), "r"(b0), "r"(b1));
}

// ---------------- device scratch (no allocations allowed) --------------------
__device__ int g_counts[N_HEADS];
__device__ int g_rows[N_HEADS * MAXM];
__device__ int g_work[64];          // (head << 16) | mtile   (BM=64 tiles)
__device__ int g_nwork;
__device__ __align__(256) __nv_bfloat16 g_Ihi[N_ROWS * DIM_D];
__device__ __align__(256) __nv_bfloat16 g_Ilo[N_ROWS * DIM_D];
// weights transposed: [head][h][d]
__device__ __align__(256) __nv_bfloat16 g_Whi[N_HEADS * DIM_H * DIM_D];
__device__ __align__(256) __nv_bfloat16 g_Wlo[N_HEADS * DIM_H * DIM_D];

__device__ __forceinline__ void split_bf16(float x, __nv_bfloat16& hi, __nv_bfloat16& lo) {
    hi = __float2bfloat16(x);
    lo = __float2bfloat16(x - __bfloat162float(hi));
}

// ============================================================================
// Fused prep kernel. 256 threads/block. Block roles by blockIdx.x:
//   [0, 4096):      weight convert + transpose (16 heads x 16x16 tiles of 32x32)
//   4096:           bucket rows by head (+ idx dtype detect) + build worklist
//   (4096, 5121):   input convert to bf16 hi/lo
// ============================================================================
#define WT_BLOCKS   (N_HEADS * 16 * 16)
#define BKT_BLOCK   WT_BLOCKS
#define IN_BLOCKS   (N_ROWS * DIM_D / 4 / 256)
#define PREP_BLOCKS (WT_BLOCKS + 1 + IN_BLOCKS)

__global__ __launch_bounds__(256)
void prep_kernel(const float* __restrict__ inp,
                 const int* __restrict__ idx32,
                 const float* __restrict__ W) {
    const int b = blockIdx.x;
    const int tid = threadIdx.x;

    if (b < WT_BLOCKS) {
        __shared__ float t[32][33];
        const int head  = b >> 8;
        const int hTile = (b >> 4) & 15;
        const int dTile = b & 15;
        const int tx = tid & 31, ty = tid >> 5;   // 32 x 8
        const float* Wh = W + (size_t)head * DIM_D * DIM_H;
        const int d0 = dTile * 32, h0 = hTile * 32;
        #pragma unroll
        for (int i = 0; i < 4; i++)
            t[ty + i * 8][tx] = Wh[(size_t)(d0 + ty + i * 8) * DIM_H + h0 + tx];
        __syncthreads();
        __nv_bfloat16* dsthi = g_Whi + (size_t)head * DIM_H * DIM_D;
        __nv_bfloat16* dstlo = g_Wlo + (size_t)head * DIM_H * DIM_D;
        #pragma unroll
        for (int i = 0; i < 4; i++) {
            int hl = ty + i * 8;
            float v = t[tx][hl];          // = W[d0+tx][h0+hl]
            __nv_bfloat16 hi, lo; split_bf16(v, hi, lo);
            size_t o = (size_t)(h0 + hl) * DIM_D + d0 + tx;
            dsthi[o] = hi; dstlo[o] = lo;
        }
    } else if (b == BKT_BLOCK) {
        __shared__ int sc[N_HEADS];
        __shared__ int any_nonzero;
        if (tid == 0) any_nonzero = 0;
        if (tid < N_HEADS) sc[tid] = 0;
        __syncthreads();
        int local = 0;
        for (int i = 1 + 2 * tid; i < N_ROWS; i += 2 * 256) local |= idx32[i];
        if (local) atomicOr(&any_nonzero, 1);
        __syncthreads();
        const int is64 = (any_nonzero == 0);
        for (int i = tid; i < N_ROWS; i += 256) {
            int h = (is64 ? idx32[2 * i] : idx32[i]) & (N_HEADS - 1);
            int pos = atomicAdd(&sc[h], 1);
            if (pos < MAXM) g_rows[h * MAXM + pos] = i;
        }
        __syncthreads();
        if (tid < N_HEADS) g_counts[tid] = min(sc[tid], MAXM);
        __syncthreads();
        if (tid == 0) {
            int n = 0;
            for (int h = 0; h < N_HEADS; h++) {
                int c = min(sc[h], MAXM);
                for (int mb = 0; mb * 64 < c; mb++) g_work[n++] = (h << 16) | mb;
            }
            g_nwork = n;   // sum ceil(nrows/64) <= 2048/64 + 16 = 48 <= 64
        }
    } else {
        const int cb = b - BKT_BLOCK - 1;
        const int e = (cb * 256 + tid) * 4;
        float4 v = *reinterpret_cast<const float4*>(inp + e);
        __nv_bfloat16 h0, l0, h1, l1, h2, l2, h3, l3;
        split_bf16(v.x, h0, l0); split_bf16(v.y, h1, l1);
        split_bf16(v.z, h2, l2); split_bf16(v.w, h3, l3);
        *reinterpret_cast<__nv_bfloat162*>(g_Ihi + e)     = __nv_bfloat162(h0, h1);
        *reinterpret_cast<__nv_bfloat162*>(g_Ihi + e + 2) = __nv_bfloat162(h2, h3);
        *reinterpret_cast<__nv_bfloat162*>(g_Ilo + e)     = __nv_bfloat162(l0, l1);
        *reinterpret_cast<__nv_bfloat162*>(g_Ilo + e + 2) = __nv_bfloat162(l2, l3);
    }
}

// ============================================================================
// HMMA GEMM, occupancy-tuned. grid = (H/32 = 16 ntiles, 64 work slots), 256 thr.
// Per CTA: D[64 rows, 32 cols], K=512, chunks of K=32, 3-stage cp.async.
// 8 warps = 4m x 2n, warp tile 16x16 (2 accumulators), pass-major hh/hl/lh.
// ============================================================================
#define BM 64
#define BN 32
#define BK 32
#define ROWB 80                    // (32+8) bf16 per smem row; multiple of 16 B
                                   // (cp.async16 alignment) and conflict-free:
                                   // 80*r mod 128, r=0..7 -> 8 distinct 16B banks
#define A_T (BM * ROWB)            // 5120 B per tile (hi or lo)
#define B_T (BN * ROWB)            // 2560
#define STAGE (2 * A_T + 2 * B_T)  // 15360
#define NSTAGE 3
#define NCHUNK (DIM_D / BK)        // 16
#define OFF_ROWS 0                 // 64 ints
#define OFF_BIAS 256               // 32 floats
#define OFF_DATA 1024
#define GEMM_SMEM (OFF_DATA + NSTAGE * STAGE)   // 47104 B

extern __shared__ char dyn_smem[];

__global__ __launch_bounds__(256, 4)
void gemm_kernel(const float* __restrict__ bias, float* __restrict__ out) {
    const int wy = blockIdx.y;
    if (wy >= g_nwork) return;
    const int item  = g_work[wy];
    const int head  = item >> 16;
    const int mbase = (item & 0xffff) * BM;
    const int nrows = g_counts[head];
    const int hbase = blockIdx.x * BN;

    const int tid  = threadIdx.x;
    const int lane = tid & 31;
    const int wid  = tid >> 5;
    const int wm   = wid & 3;        // 4 warp-rows of 16
    const int wn   = wid >> 2;       // 2 warp-cols of 16

    const uint32_t smem_u32 = smem_to_u32(dyn_smem);
    int*   s_rows = reinterpret_cast<int*>(dyn_smem + OFF_ROWS);
    float* s_bias = reinterpret_cast<float*>(dyn_smem + OFF_BIAS);
    const uint32_t data_u32 = smem_u32 + OFF_DATA;

    if (tid < BM) {
        int m = mbase + tid;
        s_rows[tid] = (m < nrows) ? g_rows[head * MAXM + m] : -1;
    }
    if (tid >= 128 && tid < 128 + BN)
        s_bias[tid - 128] = bias[head * DIM_H + hbase + (tid - 128)];
    __syncthreads();

    // ldmatrix per-lane base offsets (rows 0-15 twice; lanes>=16 take k8-15 half)
    const int lr8 = (lane & 7) + ((lane >> 3) & 1) * 8;
    const int kq  = (lane >> 4) * 16;
    const uint32_t a_off = (uint32_t)((wm * 16 + lr8) * ROWB + kq);
    const uint32_t b_off = (uint32_t)(2 * A_T + (wn * 16 + lr8) * ROWB + kq);

    const __nv_bfloat16* __restrict__ BhiP = g_Whi + ((size_t)head * DIM_H + hbase) * DIM_D;
    const __nv_bfloat16* __restrict__ BloP = g_Wlo + ((size_t)head * DIM_H + hbase) * DIM_D;

    float d[2][4];
    #pragma unroll
    for (int j = 0; j < 2; j++)
        #pragma unroll
        for (int k = 0; k < 4; k++) d[j][k] = 0.0f;

    // ---- chunk loader: A hi/lo (512 xfers) + B hi/lo (256 xfers) ----
    auto issue = [&](int ch) {
        const int koff = ch * BK;
        const uint32_t sb = data_u32 + (uint32_t)(ch % NSTAGE) * STAGE;
        #pragma unroll
        for (int j = 0; j < 2; j++) {              // A
            int u = tid + j * 256;                 // 0..511
            int tile = u >> 8;                     // 0 = hi, 1 = lo
            int w = u & 255;
            int r = w >> 2, c = w & 3;
            int grow = s_rows[r];
            const __nv_bfloat16* src =
                (tile ? g_Ilo : g_Ihi) + (size_t)max(grow, 0) * DIM_D + koff + c * 8;
            cp_async16(sb + tile * A_T + r * ROWB + c * 16, src, grow >= 0 ? 16 : 0);
        }
        {                                          // B: 256 xfers
            int u = tid;
            int tile = u >> 7;
            int w = u & 127;
            int n = w >> 2, c = w & 3;
            const __nv_bfloat16* src =
                (tile ? BloP : BhiP) + (size_t)n * DIM_D + koff + c * 8;
            cp_async16(sb + 2 * A_T + tile * B_T + n * ROWB + c * 16, src, 16);
        }
        CP_COMMIT();
    };

    issue(0);
    issue(1);
    #pragma unroll 1
    for (int it = 0; it < NCHUNK; it++) {
        __syncthreads();   // all warps done with buffer (it-1)%3 before overwrite
        if (it + 2 < NCHUNK) { issue(it + 2); CP_WAIT(2); }
        else if (it + 2 == NCHUNK) { CP_WAIT(1); }
        else { CP_WAIT(0); }
        __syncthreads();

        const uint32_t sb = data_u32 + (uint32_t)(it % NSTAGE) * STAGE;
        #pragma unroll
        for (int ks = 0; ks < BK / 16; ks++) {
            const uint32_t kb = (uint32_t)(ks * 32);
            uint32_t ah[4], al[4], bh[4], bl[4];
            {
                uint32_t ao = sb + a_off + kb;
                ldsm_x4(ah, ao);
                ldsm_x4(al, ao + A_T);
            }
            {
                uint32_t bo = sb + b_off + kb;
                ldsm_x4(bh, bo);
                ldsm_x4(bl, bo + B_T);
            }
            // pass-major over 2 independent accumulators
            mma16816(d[0], ah, bh[0], bh[2]);
            mma16816(d[1], ah, bh[1], bh[3]);
            mma16816(d[0], ah, bl[0], bl[2]);
            mma16816(d[1], ah, bl[1], bl[3]);
            mma16816(d[0], al, bh[0], bh[2]);
            mma16816(d[1], al, bh[1], bh[3]);
        }
    }

    // ---- epilogue: bias + scatter ----
    {
        const int r0 = wm * 16 + (lane >> 2);
        const int row0 = s_rows[r0];
        const int row1 = s_rows[r0 + 8];
        #pragma unroll
        for (int n2 = 0; n2 < 2; n2++) {
            const int col = wn * 16 + n2 * 8 + (lane & 3) * 2;
            const float bx = s_bias[col], by = s_bias[col + 1];
            if (row0 >= 0) {
                float2 o = make_float2(d[n2][0] + bx, d[n2][1] + by);
                *reinterpret_cast<float2*>(out + (size_t)row0 * DIM_H + hbase + col) = o;
            }
            if (row1 >= 0) {
                float2 o = make_float2(d[n2][2] + bx, d[n2][3] + by);
                *reinterpret_cast<float2*>(out + (size_t)row1 * DIM_H + hbase + col) = o;
            }
        }
    }
}

extern "C" void kernel_launch(void* const* d_in, const int* in_sizes, int n_in,
                              void* d_out, int out_size) {
    const float* inp   = (const float*)d_in[0];
    const int*   idx32 = (const int*)d_in[1];   // int64 or int32 — detected on device
    const float* W     = (const float*)d_in[2];
    const float* bias  = (const float*)d_in[3];
    float*       out   = (float*)d_out;

    cudaFuncSetAttribute(gemm_kernel, cudaFuncAttributeMaxDynamicSharedMemorySize, GEMM_SMEM);

    prep_kernel<<<PREP_BLOCKS, 256>>>(inp, idx32, W);
    dim3 grid(DIM_H / BN, 64);
    gemm_kernel<<<grid, 256, GEMM_SMEM>>>(bias, out);
}

// round 10
// speedup vs baseline: 1.1762x; 1.1762x over previous
#include <cuda_runtime.h>
#include <cuda_bf16.h>
#include <cstdint>

#define N_ROWS   2048
#define DIM_D    512
#define DIM_H    512
#define N_HEADS  16
#define MAXM     512

// ---------------- portable PTX helpers (sm_80-level only) --------------------
__device__ __forceinline__ uint32_t smem_to_u32(const void* p) {
    uint32_t a;
    asm("{ .reg .u64 t; cvta.to.shared.u64 t, %1; cvt.u32.u64 %0, t; }" : "=r"(a) : "l"(p));
    return a;
}
__device__ __forceinline__ void cp_async16(uint32_t dst, const void* src, int src_bytes) {
    asm volatile("cp.async.cg.shared.global [%0], [%1], 16, %2;"
                 :: "r"(dst), "l"(src), "r"(src_bytes) : "memory");
}
#define CP_COMMIT() asm volatile("cp.async.commit_group;" ::: "memory")
#define CP_WAIT(n)  asm volatile("cp.async.wait_group %0;" :: "n"(n) : "memory")

__device__ __forceinline__ void ldsm_x4(uint32_t* r, uint32_t addr) {
    asm volatile("ldmatrix.sync.aligned.m8n8.x4.shared.b16 {%0,%1,%2,%3}, [%4];"
                 : "=r"(r[0]), "=r"(r[1]), "=r"(r[2]), "=r"(r[3]) : "r"(addr));
}
__device__ __forceinline__ void mma16816(float* d, const uint32_t* a, uint32_t b0, uint32_t b1) {
    asm volatile("mma.sync.aligned.m16n8k16.row.col.f32.bf16.bf16.f32 "
                 "{%0,%1,%2,%3}, {%4,%5,%6,%7}, {%8,%9}, {%0,%1,%2,%3};"
                 : "+f"(d[0]), "+f"(d[1]), "+f"(d[2]), "+f"(d[3])
                 : "r"(a[0]), "r"(a[1]), "r"(a[2]), "r"(a[3]), "r"(b0), "r"(b1));
}

// ---------------- device scratch (no allocations allowed) --------------------
__device__ int g_counts[N_HEADS];
__device__ int g_rows[N_HEADS * MAXM];
__device__ int g_work[128];         // (head << 16) | mtile  (BM=32 tiles, max 80)
__device__ int g_nwork;
__device__ __align__(256) __nv_bfloat16 g_Ihi[N_ROWS * DIM_D];
__device__ __align__(256) __nv_bfloat16 g_Ilo[N_ROWS * DIM_D];
// weights transposed: [head][h][d]
__device__ __align__(256) __nv_bfloat16 g_Whi[N_HEADS * DIM_H * DIM_D];
__device__ __align__(256) __nv_bfloat16 g_Wlo[N_HEADS * DIM_H * DIM_D];

__device__ __forceinline__ void split_bf16(float x, __nv_bfloat16& hi, __nv_bfloat16& lo) {
    hi = __float2bfloat16(x);
    lo = __float2bfloat16(x - __bfloat162float(hi));
}

// ============================================================================
// Fused prep kernel (unchanged except BM=32 worklist).
// ============================================================================
#define WT_BLOCKS   (N_HEADS * 16 * 16)
#define BKT_BLOCK   WT_BLOCKS
#define IN_BLOCKS   (N_ROWS * DIM_D / 4 / 256)
#define PREP_BLOCKS (WT_BLOCKS + 1 + IN_BLOCKS)

__global__ __launch_bounds__(256)
void prep_kernel(const float* __restrict__ inp,
                 const int* __restrict__ idx32,
                 const float* __restrict__ W) {
    const int b = blockIdx.x;
    const int tid = threadIdx.x;

    if (b < WT_BLOCKS) {
        __shared__ float t[32][33];
        const int head  = b >> 8;
        const int hTile = (b >> 4) & 15;
        const int dTile = b & 15;
        const int tx = tid & 31, ty = tid >> 5;   // 32 x 8
        const float* Wh = W + (size_t)head * DIM_D * DIM_H;
        const int d0 = dTile * 32, h0 = hTile * 32;
        #pragma unroll
        for (int i = 0; i < 4; i++)
            t[ty + i * 8][tx] = Wh[(size_t)(d0 + ty + i * 8) * DIM_H + h0 + tx];
        __syncthreads();
        __nv_bfloat16* dsthi = g_Whi + (size_t)head * DIM_H * DIM_D;
        __nv_bfloat16* dstlo = g_Wlo + (size_t)head * DIM_H * DIM_D;
        #pragma unroll
        for (int i = 0; i < 4; i++) {
            int hl = ty + i * 8;
            float v = t[tx][hl];          // = W[d0+tx][h0+hl]
            __nv_bfloat16 hi, lo; split_bf16(v, hi, lo);
            size_t o = (size_t)(h0 + hl) * DIM_D + d0 + tx;
            dsthi[o] = hi; dstlo[o] = lo;
        }
    } else if (b == BKT_BLOCK) {
        __shared__ int sc[N_HEADS];
        __shared__ int any_nonzero;
        if (tid == 0) any_nonzero = 0;
        if (tid < N_HEADS) sc[tid] = 0;
        __syncthreads();
        int local = 0;
        for (int i = 1 + 2 * tid; i < N_ROWS; i += 2 * 256) local |= idx32[i];
        if (local) atomicOr(&any_nonzero, 1);
        __syncthreads();
        const int is64 = (any_nonzero == 0);
        for (int i = tid; i < N_ROWS; i += 256) {
            int h = (is64 ? idx32[2 * i] : idx32[i]) & (N_HEADS - 1);
            int pos = atomicAdd(&sc[h], 1);
            if (pos < MAXM) g_rows[h * MAXM + pos] = i;
        }
        __syncthreads();
        if (tid < N_HEADS) g_counts[tid] = min(sc[tid], MAXM);
        __syncthreads();
        if (tid == 0) {
            int n = 0;
            for (int h = 0; h < N_HEADS; h++) {
                int c = min(sc[h], MAXM);
                for (int mb = 0; mb * 32 < c; mb++) g_work[n++] = (h << 16) | mb;
            }
            g_nwork = n;   // Σceil(c/32) <= 2048/32 + 16 = 80
        }
    } else {
        const int cb = b - BKT_BLOCK - 1;
        const int e = (cb * 256 + tid) * 4;
        float4 v = *reinterpret_cast<const float4*>(inp + e);
        __nv_bfloat16 h0, l0, h1, l1, h2, l2, h3, l3;
        split_bf16(v.x, h0, l0); split_bf16(v.y, h1, l1);
        split_bf16(v.z, h2, l2); split_bf16(v.w, h3, l3);
        *reinterpret_cast<__nv_bfloat162*>(g_Ihi + e)     = __nv_bfloat162(h0, h1);
        *reinterpret_cast<__nv_bfloat162*>(g_Ihi + e + 2) = __nv_bfloat162(h2, h3);
        *reinterpret_cast<__nv_bfloat162*>(g_Ilo + e)     = __nv_bfloat162(l0, l1);
        *reinterpret_cast<__nv_bfloat162*>(g_Ilo + e + 2) = __nv_bfloat162(l2, l3);
    }
}

// ============================================================================
// HMMA GEMM, mix-tuned. grid = (H/64 = 8 ntiles, 80 work slots), 128 threads.
// Per CTA: D[32 rows, 64 cols], K=512, chunks of K=32, 3-stage cp.async,
// ONE __syncthreads per chunk. 4 warps = 2m x 2n, warp tile 16x32:
// per chunk hoist 12 ldsm, then 24 MMAs over 4 independent accumulators.
// ============================================================================
#define BM 32
#define BN 64
#define BK 32
#define ROWB 80                    // multiple of 16 (cp.async), conflict-free:
                                   // 80*r mod 128, r=0..7 -> 8 distinct 16B banks
#define A_T (BM * ROWB)            // 2560 B per tile (hi or lo)
#define B_T (BN * ROWB)            // 5120
#define STAGE (2 * A_T + 2 * B_T)  // 15360
#define NSTAGE 3
#define NCHUNK (DIM_D / BK)        // 16
#define OFF_ROWS 0                 // 32 ints
#define OFF_BIAS 128               // 64 floats
#define OFF_DATA 1024
#define GEMM_SMEM (OFF_DATA + NSTAGE * STAGE)   // 47104 B

extern __shared__ char dyn_smem[];

__global__ __launch_bounds__(128, 4)
void gemm_kernel(const float* __restrict__ bias, float* __restrict__ out) {
    const int wy = blockIdx.y;
    if (wy >= g_nwork) return;
    const int item  = g_work[wy];
    const int head  = item >> 16;
    const int mbase = (item & 0xffff) * BM;
    const int nrows = g_counts[head];
    const int hbase = blockIdx.x * BN;

    const int tid  = threadIdx.x;
    const int lane = tid & 31;
    const int wid  = tid >> 5;
    const int wm   = wid & 1;        // 2 warp-rows of 16
    const int wn   = wid >> 1;       // 2 warp-cols of 32

    const uint32_t smem_u32 = smem_to_u32(dyn_smem);
    int*   s_rows = reinterpret_cast<int*>(dyn_smem + OFF_ROWS);
    float* s_bias = reinterpret_cast<float*>(dyn_smem + OFF_BIAS);
    const uint32_t data_u32 = smem_u32 + OFF_DATA;

    if (tid < BM) {
        int m = mbase + tid;
        s_rows[tid] = (m < nrows) ? g_rows[head * MAXM + m] : -1;
    }
    if (tid >= 64 && tid < 64 + BN)
        s_bias[tid - 64] = bias[head * DIM_H + hbase + (tid - 64)];
    __syncthreads();

    // ldmatrix per-lane base offsets
    const int lr8 = (lane & 7) + ((lane >> 3) & 1) * 8;
    const int kq  = (lane >> 4) * 16;
    const uint32_t a_off = (uint32_t)((wm * 16 + lr8) * ROWB + kq);
    const uint32_t b_off = (uint32_t)(2 * A_T + (wn * 32 + lr8) * ROWB + kq);

    const __nv_bfloat16* __restrict__ BhiP = g_Whi + ((size_t)head * DIM_H + hbase) * DIM_D;
    const __nv_bfloat16* __restrict__ BloP = g_Wlo + ((size_t)head * DIM_H + hbase) * DIM_D;

    float d[4][4];
    #pragma unroll
    for (int j = 0; j < 4; j++)
        #pragma unroll
        for (int k = 0; k < 4; k++) d[j][k] = 0.0f;

    // ---- chunk loader: A hi/lo (256 xfers) + B hi/lo (512 xfers), 128 thr ----
    auto issue = [&](int ch) {
        const int koff = ch * BK;
        const uint32_t sb = data_u32 + (uint32_t)(ch % NSTAGE) * STAGE;
        #pragma unroll
        for (int j = 0; j < 2; j++) {              // A: 256
            int u = tid + j * 128;
            int tile = u >> 7;                     // 0 = hi, 1 = lo
            int w = u & 127;
            int r = w >> 2, c = w & 3;
            int grow = s_rows[r];
            const __nv_bfloat16* src =
                (tile ? g_Ilo : g_Ihi) + (size_t)max(grow, 0) * DIM_D + koff + c * 8;
            cp_async16(sb + tile * A_T + r * ROWB + c * 16, src, grow >= 0 ? 16 : 0);
        }
        #pragma unroll
        for (int j = 0; j < 4; j++) {              // B: 512
            int u = tid + j * 128;
            int tile = u >> 8;
            int w = u & 255;
            int n = w >> 2, c = w & 3;
            const __nv_bfloat16* src =
                (tile ? BloP : BhiP) + (size_t)n * DIM_D + koff + c * 8;
            cp_async16(sb + 2 * A_T + tile * B_T + n * ROWB + c * 16, src, 16);
        }
        CP_COMMIT();
    };

    issue(0);
    issue(1);
    #pragma unroll 1
    for (int it = 0; it < NCHUNK; it++) {
        if (it < NCHUNK - 1) { CP_WAIT(1); }       // stage it complete
        else                 { CP_WAIT(0); }
        __syncthreads();   // stage-it data visible to all; buffer (it-1)%3 free
        if (it + 2 < NCHUNK) issue(it + 2);

        const uint32_t sb = data_u32 + (uint32_t)(it % NSTAGE) * STAGE;
        // hoist all 12 ldsm for both k-steps, then 24 MMAs
        uint32_t ah[2][4], al[2][4], bh[2][8], bl[2][8];
        #pragma unroll
        for (int ks = 0; ks < 2; ks++) {
            const uint32_t kb = (uint32_t)(ks * 32);
            uint32_t ao = sb + a_off + kb;
            ldsm_x4(ah[ks], ao);
            ldsm_x4(al[ks], ao + A_T);
            uint32_t bo = sb + b_off + kb;
            ldsm_x4(bh[ks],     bo);
            ldsm_x4(bh[ks] + 4, bo + 16 * ROWB);
            ldsm_x4(bl[ks],     bo + B_T);
            ldsm_x4(bl[ks] + 4, bo + B_T + 16 * ROWB);
        }
        #pragma unroll
        for (int ks = 0; ks < 2; ks++) {
            // pass-major over 4 independent accumulators
            mma16816(d[0], ah[ks], bh[ks][0], bh[ks][2]);
            mma16816(d[1], ah[ks], bh[ks][1], bh[ks][3]);
            mma16816(d[2], ah[ks], bh[ks][4], bh[ks][6]);
            mma16816(d[3], ah[ks], bh[ks][5], bh[ks][7]);
            mma16816(d[0], ah[ks], bl[ks][0], bl[ks][2]);
            mma16816(d[1], ah[ks], bl[ks][1], bl[ks][3]);
            mma16816(d[2], ah[ks], bl[ks][4], bl[ks][6]);
            mma16816(d[3], ah[ks], bl[ks][5], bl[ks][7]);
            mma16816(d[0], al[ks], bh[ks][0], bh[ks][2]);
            mma16816(d[1], al[ks], bh[ks][1], bh[ks][3]);
            mma16816(d[2], al[ks], bh[ks][4], bh[ks][6]);
            mma16816(d[3], al[ks], bh[ks][5], bh[ks][7]);
        }
    }

    // ---- epilogue: bias + scatter ----
    {
        const int r0 = wm * 16 + (lane >> 2);
        const int row0 = s_rows[r0];
        const int row1 = s_rows[r0 + 8];
        #pragma unroll
        for (int n2 = 0; n2 < 4; n2++) {
            const int col = wn * 32 + n2 * 8 + (lane & 3) * 2;
            const float bx = s_bias[col], by = s_bias[col + 1];
            if (row0 >= 0) {
                float2 o = make_float2(d[n2][0] + bx, d[n2][1] + by);
                *reinterpret_cast<float2*>(out + (size_t)row0 * DIM_H + hbase + col) = o;
            }
            if (row1 >= 0) {
                float2 o = make_float2(d[n2][2] + bx, d[n2][3] + by);
                *reinterpret_cast<float2*>(out + (size_t)row1 * DIM_H + hbase + col) = o;
            }
        }
    }
}

extern "C" void kernel_launch(void* const* d_in, const int* in_sizes, int n_in,
                              void* d_out, int out_size) {
    const float* inp   = (const float*)d_in[0];
    const int*   idx32 = (const int*)d_in[1];   // int64 or int32 — detected on device
    const float* W     = (const float*)d_in[2];
    const float* bias  = (const float*)d_in[3];
    float*       out   = (float*)d_out;

    cudaFuncSetAttribute(gemm_kernel, cudaFuncAttributeMaxDynamicSharedMemorySize, GEMM_SMEM);

    prep_kernel<<<PREP_BLOCKS, 256>>>(inp, idx32, W);
    dim3 grid(DIM_H / BN, 80);   // max worklist = 2048/32 + 16 = 80
    gemm_kernel<<<grid, 128, GEMM_SMEM>>>(bias, out);
}

// round 11
// speedup vs baseline: 1.2588x; 1.0702x over previous
#include <cuda_runtime.h>
#include <cuda_fp16.h>
#include <cstdint>

#define N_ROWS   2048
#define DIM_D    512
#define DIM_H    512
#define N_HEADS  16
#define MAXM     512
#define KEXT     1024              // concat K: [Whi | Wlo]

// ---------------- portable PTX helpers (sm_80-level only) --------------------
__device__ __forceinline__ uint32_t smem_to_u32(const void* p) {
    uint32_t a;
    asm("{ .reg .u64 t; cvta.to.shared.u64 t, %1; cvt.u32.u64 %0, t; }" : "=r"(a) : "l"(p));
    return a;
}
__device__ __forceinline__ void cp_async16(uint32_t dst, const void* src, int src_bytes) {
    asm volatile("cp.async.cg.shared.global [%0], [%1], 16, %2;"
                 :: "r"(dst), "l"(src), "r"(src_bytes) : "memory");
}
#define CP_COMMIT() asm volatile("cp.async.commit_group;" ::: "memory")
#define CP_WAIT(n)  asm volatile("cp.async.wait_group %0;" :: "n"(n) : "memory")

__device__ __forceinline__ void ldsm_x4(uint32_t* r, uint32_t addr) {
    asm volatile("ldmatrix.sync.aligned.m8n8.x4.shared.b16 {%0,%1,%2,%3}, [%4];"
                 : "=r"(r[0]), "=r"(r[1]), "=r"(r[2]), "=r"(r[3]) : "r"(addr));
}
// fp16 inputs, fp32 accumulate
__device__ __forceinline__ void mma16816(float* d, const uint32_t* a, uint32_t b0, uint32_t b1) {
    asm volatile("mma.sync.aligned.m16n8k16.row.col.f32.f16.f16.f32 "
                 "{%0,%1,%2,%3}, {%4,%5,%6,%7}, {%8,%9}, {%0,%1,%2,%3};"
                 : "+f"(d[0]), "+f"(d[1]), "+f"(d[2]), "+f"(d[3])
                 : "r"(a[0]), "r"(a[1]), "r"(a[2]), "r"(a[3]), "r"(b0), "r"(b1));
}

// ---------------- device scratch (no allocations allowed) --------------------
__device__ int g_counts[N_HEADS];
__device__ int g_rows[N_HEADS * MAXM];
__device__ int g_work[128];         // (head << 16) | mtile  (BM=32 tiles, max 80)
__device__ int g_nwork;
__device__ __align__(256) __half g_Ih[N_ROWS * DIM_D];                 // inputs hi only
__device__ __align__(256) __half g_Wc[N_HEADS * DIM_H * KEXT];         // [head][h][hi 512 | lo 512]

__device__ __forceinline__ void split_f16(float x, __half& hi, __half& lo) {
    hi = __float2half(x);
    lo = __float2half(x - __half2float(hi));
}

// ============================================================================
// Fused prep kernel. 256 threads/block. Block roles by blockIdx.x:
//   [0, 4096):      weight convert + transpose -> Wcat hi/lo
//   4096:           bucket rows by head (+ idx dtype detect) + build worklist
//   (4096, 5121):   input convert to fp16 hi
// ============================================================================
#define WT_BLOCKS   (N_HEADS * 16 * 16)
#define BKT_BLOCK   WT_BLOCKS
#define IN_BLOCKS   (N_ROWS * DIM_D / 4 / 256)
#define PREP_BLOCKS (WT_BLOCKS + 1 + IN_BLOCKS)

__global__ __launch_bounds__(256)
void prep_kernel(const float* __restrict__ inp,
                 const int* __restrict__ idx32,
                 const float* __restrict__ W) {
    const int b = blockIdx.x;
    const int tid = threadIdx.x;

    if (b < WT_BLOCKS) {
        __shared__ float t[32][33];
        const int head  = b >> 8;
        const int hTile = (b >> 4) & 15;
        const int dTile = b & 15;
        const int tx = tid & 31, ty = tid >> 5;   // 32 x 8
        const float* Wh = W + (size_t)head * DIM_D * DIM_H;
        const int d0 = dTile * 32, h0 = hTile * 32;
        #pragma unroll
        for (int i = 0; i < 4; i++)
            t[ty + i * 8][tx] = Wh[(size_t)(d0 + ty + i * 8) * DIM_H + h0 + tx];
        __syncthreads();
        __half* dst = g_Wc + (size_t)head * DIM_H * KEXT;
        #pragma unroll
        for (int i = 0; i < 4; i++) {
            int hl = ty + i * 8;
            float v = t[tx][hl];          // = W[d0+tx][h0+hl]
            __half hi, lo; split_f16(v, hi, lo);
            size_t o = (size_t)(h0 + hl) * KEXT + d0 + tx;
            dst[o] = hi;                  // cols [0,512) = hi
            dst[o + DIM_D] = lo;          // cols [512,1024) = lo
        }
    } else if (b == BKT_BLOCK) {
        __shared__ int sc[N_HEADS];
        __shared__ int any_nonzero;
        if (tid == 0) any_nonzero = 0;
        if (tid < N_HEADS) sc[tid] = 0;
        __syncthreads();
        int local = 0;
        for (int i = 1 + 2 * tid; i < N_ROWS; i += 2 * 256) local |= idx32[i];
        if (local) atomicOr(&any_nonzero, 1);
        __syncthreads();
        const int is64 = (any_nonzero == 0);
        for (int i = tid; i < N_ROWS; i += 256) {
            int h = (is64 ? idx32[2 * i] : idx32[i]) & (N_HEADS - 1);
            int pos = atomicAdd(&sc[h], 1);
            if (pos < MAXM) g_rows[h * MAXM + pos] = i;
        }
        __syncthreads();
        if (tid < N_HEADS) g_counts[tid] = min(sc[tid], MAXM);
        __syncthreads();
        if (tid == 0) {
            int n = 0;
            for (int h = 0; h < N_HEADS; h++) {
                int c = min(sc[h], MAXM);
                for (int mb = 0; mb * 32 < c; mb++) g_work[n++] = (h << 16) | mb;
            }
            g_nwork = n;   // Σceil(c/32) <= 2048/32 + 16 = 80
        }
    } else {
        const int cb = b - BKT_BLOCK - 1;
        const int e = (cb * 256 + tid) * 4;
        float4 v = *reinterpret_cast<const float4*>(inp + e);
        __half2 h01 = __halves2half2(__float2half(v.x), __float2half(v.y));
        __half2 h23 = __halves2half2(__float2half(v.z), __float2half(v.w));
        *reinterpret_cast<__half2*>(g_Ih + e)     = h01;
        *reinterpret_cast<__half2*>(g_Ih + e + 2) = h23;
    }
}

// ============================================================================
// fp16 concat-K HMMA GEMM. grid = (H/64 = 8 ntiles, 80 work slots), 128 thr.
// Per CTA: D[32 rows, 64 cols], Kext=1024 (A wraps mod 512), chunks of K=64,
// 3-stage cp.async, one __syncthreads per chunk.
// 4 warps = 2m x 2n, warp tile 16x32, 4 independent accumulators.
// ============================================================================
#define BM 32
#define BN 64
#define BK 64
#define ROWB 144                   // 64 fp16 = 128B + 16B pad; mult of 16;
                                   // 144*r mod 128, r=0..7 -> 8 distinct banks
#define A_T (BM * ROWB)            // 4608 B
#define B_T (BN * ROWB)            // 9216 B
#define STAGE (A_T + B_T)          // 13824
#define NSTAGE 3
#define NCHUNK (KEXT / BK)         // 16
#define OFF_ROWS 0                 // 32 ints
#define OFF_BIAS 128               // 64 floats
#define OFF_DATA 1024
#define GEMM_SMEM (OFF_DATA + NSTAGE * STAGE)   // 42496 B

extern __shared__ char dyn_smem[];

__global__ __launch_bounds__(128, 4)
void gemm_kernel(const float* __restrict__ bias, float* __restrict__ out) {
    const int wy = blockIdx.y;
    if (wy >= g_nwork) return;
    const int item  = g_work[wy];
    const int head  = item >> 16;
    const int mbase = (item & 0xffff) * BM;
    const int nrows = g_counts[head];
    const int hbase = blockIdx.x * BN;

    const int tid  = threadIdx.x;
    const int lane = tid & 31;
    const int wid  = tid >> 5;
    const int wm   = wid & 1;        // 2 warp-rows of 16
    const int wn   = wid >> 1;       // 2 warp-cols of 32

    const uint32_t smem_u32 = smem_to_u32(dyn_smem);
    int*   s_rows = reinterpret_cast<int*>(dyn_smem + OFF_ROWS);
    float* s_bias = reinterpret_cast<float*>(dyn_smem + OFF_BIAS);
    const uint32_t data_u32 = smem_u32 + OFF_DATA;

    if (tid < BM) {
        int m = mbase + tid;
        s_rows[tid] = (m < nrows) ? g_rows[head * MAXM + m] : -1;
    }
    if (tid >= 64 && tid < 64 + BN)
        s_bias[tid - 64] = bias[head * DIM_H + hbase + (tid - 64)];
    __syncthreads();

    // ldmatrix per-lane base offsets
    const int lr8 = (lane & 7) + ((lane >> 3) & 1) * 8;
    const int kq  = (lane >> 4) * 16;
    const uint32_t a_off = (uint32_t)((wm * 16 + lr8) * ROWB + kq);
    const uint32_t b_off = (uint32_t)(A_T + (wn * 32 + lr8) * ROWB + kq);

    const __half* __restrict__ BcP = g_Wc + ((size_t)head * DIM_H + hbase) * KEXT;

    float d[4][4];
    #pragma unroll
    for (int j = 0; j < 4; j++)
        #pragma unroll
        for (int k = 0; k < 4; k++) d[j][k] = 0.0f;

    // ---- chunk loader: A (256 xfers, wraps mod 512) + B (512 xfers) ----
    auto issue = [&](int ch) {
        const int koffA = (ch * BK) & (DIM_D - 1);   // A wraps: chunks 8..15 reread
        const int koffB = ch * BK;                   // B spans full 1024 concat-K
        const uint32_t sb = data_u32 + (uint32_t)(ch % NSTAGE) * STAGE;
        #pragma unroll
        for (int j = 0; j < 2; j++) {                // A: 32 rows x 8 x 16B
            int u = tid + j * 128;
            int r = u >> 3, c = u & 7;
            int grow = s_rows[r];
            const __half* src = g_Ih + (size_t)max(grow, 0) * DIM_D + koffA + c * 8;
            cp_async16(sb + r * ROWB + c * 16, src, grow >= 0 ? 16 : 0);
        }
        #pragma unroll
        for (int j = 0; j < 4; j++) {                // B: 64 rows x 8 x 16B
            int u = tid + j * 128;
            int n = u >> 3, c = u & 7;
            const __half* src = BcP + (size_t)n * KEXT + koffB + c * 8;
            cp_async16(sb + A_T + n * ROWB + c * 16, src, 16);
        }
        CP_COMMIT();
    };

    issue(0);
    issue(1);
    #pragma unroll 1
    for (int it = 0; it < NCHUNK; it++) {
        if (it < NCHUNK - 1) { CP_WAIT(1); }
        else                 { CP_WAIT(0); }
        __syncthreads();   // stage-it data visible; buffer (it-1)%3 free
        if (it + 2 < NCHUNK) issue(it + 2);

        const uint32_t sb = data_u32 + (uint32_t)(it % NSTAGE) * STAGE;
        // 4 k16-steps: process in 2 halves; hoist ldsm per half, then MMAs
        #pragma unroll
        for (int half = 0; half < 2; half++) {
            uint32_t a[2][4], bb[2][8];
            #pragma unroll
            for (int q = 0; q < 2; q++) {
                const uint32_t kb = (uint32_t)((half * 2 + q) * 32);
                ldsm_x4(a[q], sb + a_off + kb);
                uint32_t bo = sb + b_off + kb;
                ldsm_x4(bb[q],     bo);
                ldsm_x4(bb[q] + 4, bo + 16 * ROWB);
            }
            #pragma unroll
            for (int q = 0; q < 2; q++) {
                // 4 independent accumulators per k-step
                mma16816(d[0], a[q], bb[q][0], bb[q][2]);
                mma16816(d[1], a[q], bb[q][1], bb[q][3]);
                mma16816(d[2], a[q], bb[q][4], bb[q][6]);
                mma16816(d[3], a[q], bb[q][5], bb[q][7]);
            }
        }
    }

    // ---- epilogue: bias + scatter ----
    {
        const int r0 = wm * 16 + (lane >> 2);
        const int row0 = s_rows[r0];
        const int row1 = s_rows[r0 + 8];
        #pragma unroll
        for (int n2 = 0; n2 < 4; n2++) {
            const int col = wn * 32 + n2 * 8 + (lane & 3) * 2;
            const float bx = s_bias[col], by = s_bias[col + 1];
            if (row0 >= 0) {
                float2 o = make_float2(d[n2][0] + bx, d[n2][1] + by);
                *reinterpret_cast<float2*>(out + (size_t)row0 * DIM_H + hbase + col) = o;
            }
            if (row1 >= 0) {
                float2 o = make_float2(d[n2][2] + bx, d[n2][3] + by);
                *reinterpret_cast<float2*>(out + (size_t)row1 * DIM_H + hbase + col) = o;
            }
        }
    }
}

extern "C" void kernel_launch(void* const* d_in, const int* in_sizes, int n_in,
                              void* d_out, int out_size) {
    const float* inp   = (const float*)d_in[0];
    const int*   idx32 = (const int*)d_in[1];   // int64 or int32 — detected on device
    const float* W     = (const float*)d_in[2];
    const float* bias  = (const float*)d_in[3];
    float*       out   = (float*)d_out;

    cudaFuncSetAttribute(gemm_kernel, cudaFuncAttributeMaxDynamicSharedMemorySize, GEMM_SMEM);

    prep_kernel<<<PREP_BLOCKS, 256>>>(inp, idx32, W);
    dim3 grid(DIM_H / BN, 80);   // max worklist = 2048/32 + 16 = 80
    gemm_kernel<<<grid, 128, GEMM_SMEM>>>(bias, out);
}

// round 12
// speedup vs baseline: 1.2870x; 1.0224x over previous
#include <cuda_runtime.h>
#include <cuda_fp16.h>
#include <cstdint>

#define N_ROWS   2048
#define DIM_D    512
#define DIM_H    512
#define N_HEADS  16
#define MAXM     512
#define KEXT     1024              // concat K: [Whi | Wlo]

// ---------------- portable PTX helpers (sm_80-level only) --------------------
__device__ __forceinline__ uint32_t smem_to_u32(const void* p) {
    uint32_t a;
    asm("{ .reg .u64 t; cvta.to.shared.u64 t, %1; cvt.u32.u64 %0, t; }" : "=r"(a) : "l"(p));
    return a;
}
__device__ __forceinline__ void cp_async16(uint32_t dst, const void* src, int src_bytes) {
    asm volatile("cp.async.cg.shared.global [%0], [%1], 16, %2;"
                 :: "r"(dst), "l"(src), "r"(src_bytes) : "memory");
}
#define CP_COMMIT() asm volatile("cp.async.commit_group;" ::: "memory")
#define CP_WAIT(n)  asm volatile("cp.async.wait_group %0;" :: "n"(n) : "memory")

__device__ __forceinline__ void ldsm_x4(uint32_t* r, uint32_t addr) {
    asm volatile("ldmatrix.sync.aligned.m8n8.x4.shared.b16 {%0,%1,%2,%3}, [%4];"
                 : "=r"(r[0]), "=r"(r[1]), "=r"(r[2]), "=r"(r[3]) : "r"(addr));
}
// fp16 inputs, fp32 accumulate
__device__ __forceinline__ void mma16816(float* d, const uint32_t* a, uint32_t b0, uint32_t b1) {
    asm volatile("mma.sync.aligned.m16n8k16.row.col.f32.f16.f16.f32 "
                 "{%0,%1,%2,%3}, {%4,%5,%6,%7}, {%8,%9}, {%0,%1,%2,%3};"
                 : "+f"(d[0]), "+f"(d[1]), "+f"(d[2]), "+f"(d[3])
                 : "r"(a[0]), "r"(a[1]), "r"(a[2]), "r"(a[3]), "r"(b0), "r"(b1));
}

// ---------------- device scratch (no allocations allowed) --------------------
__device__ int g_counts[N_HEADS];
__device__ int g_rows[N_HEADS * MAXM];
__device__ int g_work[64];          // (head << 16) | mtile  (BM=64 tiles, max 48)
__device__ int g_nwork;
__device__ __align__(256) __half g_Ih[N_ROWS * DIM_D];                 // inputs hi only
__device__ __align__(256) __half g_Wc[N_HEADS * DIM_H * KEXT];         // [head][h][hi 512 | lo 512]

__device__ __forceinline__ void split_f16(float x, __half& hi, __half& lo) {
    hi = __float2half(x);
    lo = __float2half(x - __half2float(hi));
}

// ============================================================================
// Fused prep kernel. 256 threads/block. Block roles by blockIdx.x:
//   [0, 4096):      weight convert + transpose -> Wcat hi/lo
//   4096:           bucket rows by head (+ idx dtype detect) + build worklist
//   (4096, 5121):   input convert to fp16 hi
// ============================================================================
#define WT_BLOCKS   (N_HEADS * 16 * 16)
#define BKT_BLOCK   WT_BLOCKS
#define IN_BLOCKS   (N_ROWS * DIM_D / 4 / 256)
#define PREP_BLOCKS (WT_BLOCKS + 1 + IN_BLOCKS)

__global__ __launch_bounds__(256)
void prep_kernel(const float* __restrict__ inp,
                 const int* __restrict__ idx32,
                 const float* __restrict__ W) {
    const int b = blockIdx.x;
    const int tid = threadIdx.x;

    if (b < WT_BLOCKS) {
        __shared__ float t[32][33];
        const int head  = b >> 8;
        const int hTile = (b >> 4) & 15;
        const int dTile = b & 15;
        const int tx = tid & 31, ty = tid >> 5;   // 32 x 8
        const float* Wh = W + (size_t)head * DIM_D * DIM_H;
        const int d0 = dTile * 32, h0 = hTile * 32;
        #pragma unroll
        for (int i = 0; i < 4; i++)
            t[ty + i * 8][tx] = Wh[(size_t)(d0 + ty + i * 8) * DIM_H + h0 + tx];
        __syncthreads();
        __half* dst = g_Wc + (size_t)head * DIM_H * KEXT;
        #pragma unroll
        for (int i = 0; i < 4; i++) {
            int hl = ty + i * 8;
            float v = t[tx][hl];          // = W[d0+tx][h0+hl]
            __half hi, lo; split_f16(v, hi, lo);
            size_t o = (size_t)(h0 + hl) * KEXT + d0 + tx;
            dst[o] = hi;                  // cols [0,512) = hi
            dst[o + DIM_D] = lo;          // cols [512,1024) = lo
        }
    } else if (b == BKT_BLOCK) {
        __shared__ int sc[N_HEADS];
        __shared__ int any_nonzero;
        if (tid == 0) any_nonzero = 0;
        if (tid < N_HEADS) sc[tid] = 0;
        __syncthreads();
        int local = 0;
        for (int i = 1 + 2 * tid; i < N_ROWS; i += 2 * 256) local |= idx32[i];
        if (local) atomicOr(&any_nonzero, 1);
        __syncthreads();
        const int is64 = (any_nonzero == 0);
        for (int i = tid; i < N_ROWS; i += 256) {
            int h = (is64 ? idx32[2 * i] : idx32[i]) & (N_HEADS - 1);
            int pos = atomicAdd(&sc[h], 1);
            if (pos < MAXM) g_rows[h * MAXM + pos] = i;
        }
        __syncthreads();
        if (tid < N_HEADS) g_counts[tid] = min(sc[tid], MAXM);
        __syncthreads();
        if (tid == 0) {
            int n = 0;
            for (int h = 0; h < N_HEADS; h++) {
                int c = min(sc[h], MAXM);
                for (int mb = 0; mb * 64 < c; mb++) g_work[n++] = (h << 16) | mb;
            }
            g_nwork = n;   // Σceil(c/64) <= 2048/64 + 16 = 48
        }
    } else {
        const int cb = b - BKT_BLOCK - 1;
        const int e = (cb * 256 + tid) * 4;
        float4 v = *reinterpret_cast<const float4*>(inp + e);
        __half2 h01 = __halves2half2(__float2half(v.x), __float2half(v.y));
        __half2 h23 = __halves2half2(__float2half(v.z), __float2half(v.w));
        *reinterpret_cast<__half2*>(g_Ih + e)     = h01;
        *reinterpret_cast<__half2*>(g_Ih + e + 2) = h23;
    }
}

// ============================================================================
// fp16 concat-K HMMA GEMM. grid = (H/64 = 8 ntiles, 48 work slots), 128 thr.
// Per CTA: D[64 rows, 64 cols], Kext=1024 (A wraps mod 512), chunks of K=64,
// 3-stage cp.async, one __syncthreads per chunk.
// 4 warps = 2m x 2n, warp tile 32x32: per k16-step 4 ldsm -> 8 independent MMAs.
// ============================================================================
#define BM 64
#define BN 64
#define BK 64
#define ROWB 144                   // 64 fp16 = 128B + 16B pad; mult of 16;
                                   // 144*r mod 128, r=0..7 -> 8 distinct banks
#define A_T (BM * ROWB)            // 9216 B
#define B_T (BN * ROWB)            // 9216 B
#define STAGE (A_T + B_T)          // 18432
#define NSTAGE 3
#define NCHUNK (KEXT / BK)         // 16
#define OFF_ROWS 0                 // 64 ints
#define OFF_BIAS 256               // 64 floats
#define OFF_DATA 1024
#define GEMM_SMEM (OFF_DATA + NSTAGE * STAGE)   // 56320 B

extern __shared__ char dyn_smem[];

__global__ __launch_bounds__(128, 4)
void gemm_kernel(const float* __restrict__ bias, float* __restrict__ out) {
    const int wy = blockIdx.y;
    if (wy >= g_nwork) return;
    const int item  = g_work[wy];
    const int head  = item >> 16;
    const int mbase = (item & 0xffff) * BM;
    const int nrows = g_counts[head];
    const int hbase = blockIdx.x * BN;

    const int tid  = threadIdx.x;
    const int lane = tid & 31;
    const int wid  = tid >> 5;
    const int wm   = wid & 1;        // 2 warp-rows of 32
    const int wn   = wid >> 1;       // 2 warp-cols of 32

    const uint32_t smem_u32 = smem_to_u32(dyn_smem);
    int*   s_rows = reinterpret_cast<int*>(dyn_smem + OFF_ROWS);
    float* s_bias = reinterpret_cast<float*>(dyn_smem + OFF_BIAS);
    const uint32_t data_u32 = smem_u32 + OFF_DATA;

    if (tid < BM) {
        int m = mbase + tid;
        s_rows[tid] = (m < nrows) ? g_rows[head * MAXM + m] : -1;
    }
    if (tid >= 64 && tid < 64 + BN)
        s_bias[tid - 64] = bias[head * DIM_H + hbase + (tid - 64)];
    __syncthreads();

    // ldmatrix per-lane base offsets
    const int lr8 = (lane & 7) + ((lane >> 3) & 1) * 8;
    const int kq  = (lane >> 4) * 16;
    const uint32_t a_off = (uint32_t)((wm * 32 + lr8) * ROWB + kq);
    const uint32_t b_off = (uint32_t)(A_T + (wn * 32 + lr8) * ROWB + kq);

    const __half* __restrict__ BcP = g_Wc + ((size_t)head * DIM_H + hbase) * KEXT;

    float d[2][4][4];                 // [m-tile][n8-group][frag]
    #pragma unroll
    for (int i = 0; i < 2; i++)
        #pragma unroll
        for (int j = 0; j < 4; j++)
            #pragma unroll
            for (int k = 0; k < 4; k++) d[i][j][k] = 0.0f;

    // ---- chunk loader: A (512 xfers, wraps mod 512) + B (512 xfers) ----
    auto issue = [&](int ch) {
        const int koffA = (ch * BK) & (DIM_D - 1);   // A wraps: chunks 8..15 reread
        const int koffB = ch * BK;                   // B spans full 1024 concat-K
        const uint32_t sb = data_u32 + (uint32_t)(ch % NSTAGE) * STAGE;
        #pragma unroll
        for (int j = 0; j < 4; j++) {                // A: 64 rows x 8 x 16B
            int u = tid + j * 128;
            int r = u >> 3, c = u & 7;
            int grow = s_rows[r];
            const __half* src = g_Ih + (size_t)max(grow, 0) * DIM_D + koffA + c * 8;
            cp_async16(sb + r * ROWB + c * 16, src, grow >= 0 ? 16 : 0);
        }
        #pragma unroll
        for (int j = 0; j < 4; j++) {                // B: 64 rows x 8 x 16B
            int u = tid + j * 128;
            int n = u >> 3, c = u & 7;
            const __half* src = BcP + (size_t)n * KEXT + koffB + c * 8;
            cp_async16(sb + A_T + n * ROWB + c * 16, src, 16);
        }
        CP_COMMIT();
    };

    issue(0);
    issue(1);
    #pragma unroll 1
    for (int it = 0; it < NCHUNK; it++) {
        if (it < NCHUNK - 1) { CP_WAIT(1); }
        else                 { CP_WAIT(0); }
        __syncthreads();   // stage-it data visible; buffer (it-1)%3 free
        if (it + 2 < NCHUNK) issue(it + 2);

        const uint32_t sb = data_u32 + (uint32_t)(it % NSTAGE) * STAGE;
        #pragma unroll
        for (int ks = 0; ks < BK / 16; ks++) {
            const uint32_t kb = (uint32_t)(ks * 32);
            // 4 ldsm -> 8 independent MMAs
            uint32_t a0[4], a1[4], b0[4], b1[4];
            uint32_t ao = sb + a_off + kb;
            uint32_t bo = sb + b_off + kb;
            ldsm_x4(a0, ao);                 // m rows [wm*32,   +16)
            ldsm_x4(a1, ao + 16 * ROWB);     // m rows [wm*32+16, +16)
            ldsm_x4(b0, bo);                 // n cols [wn*32,   +16)
            ldsm_x4(b1, bo + 16 * ROWB);     // n cols [wn*32+16, +16)
            // b reg layout: [0]=n(0:8)k(0:8), [1]=n(8:16)k(0:8), [2]=n(0:8)k(8:16), [3]=n(8:16)k(8:16)
            mma16816(d[0][0], a0, b0[0], b0[2]);
            mma16816(d[0][1], a0, b0[1], b0[3]);
            mma16816(d[0][2], a0, b1[0], b1[2]);
            mma16816(d[0][3], a0, b1[1], b1[3]);
            mma16816(d[1][0], a1, b0[0], b0[2]);
            mma16816(d[1][1], a1, b0[1], b0[3]);
            mma16816(d[1][2], a1, b1[0], b1[2]);
            mma16816(d[1][3], a1, b1[1], b1[3]);
        }
    }

    // ---- epilogue: bias + scatter ----
    #pragma unroll
    for (int m2 = 0; m2 < 2; m2++) {
        const int r0 = wm * 32 + m2 * 16 + (lane >> 2);
        const int row0 = s_rows[r0];
        const int row1 = s_rows[r0 + 8];
        #pragma unroll
        for (int n2 = 0; n2 < 4; n2++) {
            const int col = wn * 32 + n2 * 8 + (lane & 3) * 2;
            const float bx = s_bias[col], by = s_bias[col + 1];
            if (row0 >= 0) {
                float2 o = make_float2(d[m2][n2][0] + bx, d[m2][n2][1] + by);
                *reinterpret_cast<float2*>(out + (size_t)row0 * DIM_H + hbase + col) = o;
            }
            if (row1 >= 0) {
                float2 o = make_float2(d[m2][n2][2] + bx, d[m2][n2][3] + by);
                *reinterpret_cast<float2*>(out + (size_t)row1 * DIM_H + hbase + col) = o;
            }
        }
    }
}

extern "C" void kernel_launch(void* const* d_in, const int* in_sizes, int n_in,
                              void* d_out, int out_size) {
    const float* inp   = (const float*)d_in[0];
    const int*   idx32 = (const int*)d_in[1];   // int64 or int32 — detected on device
    const float* W     = (const float*)d_in[2];
    const float* bias  = (const float*)d_in[3];
    float*       out   = (float*)d_out;

    cudaFuncSetAttribute(gemm_kernel, cudaFuncAttributeMaxDynamicSharedMemorySize, GEMM_SMEM);

    prep_kernel<<<PREP_BLOCKS, 256>>>(inp, idx32, W);
    dim3 grid(DIM_H / BN, 48);   // max worklist = 2048/64 + 16 = 48
    gemm_kernel<<<grid, 128, GEMM_SMEM>>>(bias, out);
}

// round 13
// speedup vs baseline: 1.7315x; 1.3454x over previous
#include <cuda_runtime.h>
#include <cuda_fp16.h>
#include <cstdint>

#define N_ROWS   2048
#define DIM_D    512
#define DIM_H    512
#define N_HEADS  16
#define MAXM     512

// ---------------- portable PTX helpers (sm_80-level only) --------------------
__device__ __forceinline__ uint32_t smem_to_u32(const void* p) {
    uint32_t a;
    asm("{ .reg .u64 t; cvta.to.shared.u64 t, %1; cvt.u32.u64 %0, t; }" : "=r"(a) : "l"(p));
    return a;
}
__device__ __forceinline__ void cp_async16(uint32_t dst, const void* src, int src_bytes) {
    asm volatile("cp.async.cg.shared.global [%0], [%1], 16, %2;"
                 :: "r"(dst), "l"(src), "r"(src_bytes) : "memory");
}
#define CP_COMMIT() asm volatile("cp.async.commit_group;" ::: "memory")
#define CP_WAIT(n)  asm volatile("cp.async.wait_group %0;" :: "n"(n) : "memory")

__device__ __forceinline__ void ldsm_x4(uint32_t* r, uint32_t addr) {
    asm volatile("ldmatrix.sync.aligned.m8n8.x4.shared.b16 {%0,%1,%2,%3}, [%4];"
                 : "=r"(r[0]), "=r"(r[1]), "=r"(r[2]), "=r"(r[3]) : "r"(addr));
}
// fp16 inputs, fp32 accumulate
__device__ __forceinline__ void mma16816(float* d, const uint32_t* a, uint32_t b0, uint32_t b1) {
    asm volatile("mma.sync.aligned.m16n8k16.row.col.f32.f16.f16.f32 "
                 "{%0,%1,%2,%3}, {%4,%5,%6,%7}, {%8,%9}, {%0,%1,%2,%3};"
                 : "+f"(d[0]), "+f"(d[1]), "+f"(d[2]), "+f"(d[3])
                 : "r"(a[0]), "r"(a[1]), "r"(a[2]), "r"(a[3]), "r"(b0), "r"(b1));
}

// ---------------- device scratch (no allocations allowed) --------------------
__device__ int g_counts[N_HEADS];
__device__ int g_rows[N_HEADS * MAXM];
__device__ int g_work[64];          // (head << 16) | mtile  (BM=64 tiles, max 48)
__device__ int g_nwork;
__device__ __align__(256) __half g_Ih[N_ROWS * DIM_D];            // inputs fp16
__device__ __align__(256) __half g_Wt[N_HEADS * DIM_H * DIM_D];   // W^T fp16 [head][h][d]

// ============================================================================
// Fused prep kernel. 256 threads/block. Block roles by blockIdx.x:
//   [0, 4096):      weight convert + transpose -> Wt fp16
//   4096:           bucket rows by head (+ idx dtype detect) + build worklist
//   (4096, 5121):   input convert to fp16
// ============================================================================
#define WT_BLOCKS   (N_HEADS * 16 * 16)
#define BKT_BLOCK   WT_BLOCKS
#define IN_BLOCKS   (N_ROWS * DIM_D / 4 / 256)
#define PREP_BLOCKS (WT_BLOCKS + 1 + IN_BLOCKS)

__global__ __launch_bounds__(256)
void prep_kernel(const float* __restrict__ inp,
                 const int* __restrict__ idx32,
                 const float* __restrict__ W) {
    const int b = blockIdx.x;
    const int tid = threadIdx.x;

    if (b < WT_BLOCKS) {
        __shared__ float t[32][33];
        const int head  = b >> 8;
        const int hTile = (b >> 4) & 15;
        const int dTile = b & 15;
        const int tx = tid & 31, ty = tid >> 5;   // 32 x 8
        const float* Wh = W + (size_t)head * DIM_D * DIM_H;
        const int d0 = dTile * 32, h0 = hTile * 32;
        #pragma unroll
        for (int i = 0; i < 4; i++)
            t[ty + i * 8][tx] = Wh[(size_t)(d0 + ty + i * 8) * DIM_H + h0 + tx];
        __syncthreads();
        __half* dst = g_Wt + (size_t)head * DIM_H * DIM_D;
        #pragma unroll
        for (int i = 0; i < 4; i++) {
            int hl = ty + i * 8;
            float v = t[tx][hl];          // = W[d0+tx][h0+hl]
            dst[(size_t)(h0 + hl) * DIM_D + d0 + tx] = __float2half(v);
        }
    } else if (b == BKT_BLOCK) {
        __shared__ int sc[N_HEADS];
        __shared__ int any_nonzero;
        if (tid == 0) any_nonzero = 0;
        if (tid < N_HEADS) sc[tid] = 0;
        __syncthreads();
        int local = 0;
        for (int i = 1 + 2 * tid; i < N_ROWS; i += 2 * 256) local |= idx32[i];
        if (local) atomicOr(&any_nonzero, 1);
        __syncthreads();
        const int is64 = (any_nonzero == 0);
        for (int i = tid; i < N_ROWS; i += 256) {
            int h = (is64 ? idx32[2 * i] : idx32[i]) & (N_HEADS - 1);
            int pos = atomicAdd(&sc[h], 1);
            if (pos < MAXM) g_rows[h * MAXM + pos] = i;
        }
        __syncthreads();
        if (tid < N_HEADS) g_counts[tid] = min(sc[tid], MAXM);
        __syncthreads();
        if (tid == 0) {
            int n = 0;
            for (int h = 0; h < N_HEADS; h++) {
                int c = min(sc[h], MAXM);
                for (int mb = 0; mb * 64 < c; mb++) g_work[n++] = (h << 16) | mb;
            }
            g_nwork = n;   // Σceil(c/64) <= 2048/64 + 16 = 48
        }
    } else {
        const int cb = b - BKT_BLOCK - 1;
        const int e = (cb * 256 + tid) * 4;
        float4 v = *reinterpret_cast<const float4*>(inp + e);
        __half2 h01 = __halves2half2(__float2half(v.x), __float2half(v.y));
        __half2 h23 = __halves2half2(__float2half(v.z), __float2half(v.w));
        *reinterpret_cast<__half2*>(g_Ih + e)     = h01;
        *reinterpret_cast<__half2*>(g_Ih + e + 2) = h23;
    }
}

// ============================================================================
// Single-pass fp16 HMMA GEMM. grid = (H/64 = 8 ntiles, 48 work slots), 128 thr.
// Per CTA: D[64 rows, 64 cols], K=512, chunks of K=64 (8 chunks),
// 3-stage cp.async, one __syncthreads per chunk.
// 4 warps = 2m x 2n, warp tile 32x32: per k16-step 4 ldsm -> 8 independent MMAs.
// ============================================================================
#define BM 64
#define BN 64
#define BK 64
#define ROWB 144                   // 64 fp16 = 128B + 16B pad; mult of 16;
                                   // 144*r mod 128, r=0..7 -> 8 distinct banks
#define A_T (BM * ROWB)            // 9216 B
#define B_T (BN * ROWB)            // 9216 B
#define STAGE (A_T + B_T)          // 18432
#define NSTAGE 3
#define NCHUNK (DIM_D / BK)        // 8
#define OFF_ROWS 0                 // 64 ints
#define OFF_BIAS 256               // 64 floats
#define OFF_DATA 1024
#define GEMM_SMEM (OFF_DATA + NSTAGE * STAGE)   // 56320 B

extern __shared__ char dyn_smem[];

__global__ __launch_bounds__(128, 4)
void gemm_kernel(const float* __restrict__ bias, float* __restrict__ out) {
    const int wy = blockIdx.y;
    if (wy >= g_nwork) return;
    const int item  = g_work[wy];
    const int head  = item >> 16;
    const int mbase = (item & 0xffff) * BM;
    const int nrows = g_counts[head];
    const int hbase = blockIdx.x * BN;

    const int tid  = threadIdx.x;
    const int lane = tid & 31;
    const int wid  = tid >> 5;
    const int wm   = wid & 1;        // 2 warp-rows of 32
    const int wn   = wid >> 1;       // 2 warp-cols of 32

    const uint32_t smem_u32 = smem_to_u32(dyn_smem);
    int*   s_rows = reinterpret_cast<int*>(dyn_smem + OFF_ROWS);
    float* s_bias = reinterpret_cast<float*>(dyn_smem + OFF_BIAS);
    const uint32_t data_u32 = smem_u32 + OFF_DATA;

    if (tid < BM) {
        int m = mbase + tid;
        s_rows[tid] = (m < nrows) ? g_rows[head * MAXM + m] : -1;
    }
    if (tid >= 64 && tid < 64 + BN)
        s_bias[tid - 64] = bias[head * DIM_H + hbase + (tid - 64)];
    __syncthreads();

    // ldmatrix per-lane base offsets
    const int lr8 = (lane & 7) + ((lane >> 3) & 1) * 8;
    const int kq  = (lane >> 4) * 16;
    const uint32_t a_off = (uint32_t)((wm * 32 + lr8) * ROWB + kq);
    const uint32_t b_off = (uint32_t)(A_T + (wn * 32 + lr8) * ROWB + kq);

    const __half* __restrict__ BtP = g_Wt + ((size_t)head * DIM_H + hbase) * DIM_D;

    float d[2][4][4];                 // [m-tile][n8-group][frag]
    #pragma unroll
    for (int i = 0; i < 2; i++)
        #pragma unroll
        for (int j = 0; j < 4; j++)
            #pragma unroll
            for (int k = 0; k < 4; k++) d[i][j][k] = 0.0f;

    // ---- chunk loader: A (512 xfers) + B (512 xfers) ----
    auto issue = [&](int ch) {
        const int koff = ch * BK;
        const uint32_t sb = data_u32 + (uint32_t)(ch % NSTAGE) * STAGE;
        #pragma unroll
        for (int j = 0; j < 4; j++) {                // A: 64 rows x 8 x 16B
            int u = tid + j * 128;
            int r = u >> 3, c = u & 7;
            int grow = s_rows[r];
            const __half* src = g_Ih + (size_t)max(grow, 0) * DIM_D + koff + c * 8;
            cp_async16(sb + r * ROWB + c * 16, src, grow >= 0 ? 16 : 0);
        }
        #pragma unroll
        for (int j = 0; j < 4; j++) {                // B: 64 rows x 8 x 16B
            int u = tid + j * 128;
            int n = u >> 3, c = u & 7;
            const __half* src = BtP + (size_t)n * DIM_D + koff + c * 8;
            cp_async16(sb + A_T + n * ROWB + c * 16, src, 16);
        }
        CP_COMMIT();
    };

    issue(0);
    issue(1);
    #pragma unroll 1
    for (int it = 0; it < NCHUNK; it++) {
        if (it < NCHUNK - 1) { CP_WAIT(1); }
        else                 { CP_WAIT(0); }
        __syncthreads();   // stage-it data visible; buffer (it-1)%3 free
        if (it + 2 < NCHUNK) issue(it + 2);

        const uint32_t sb = data_u32 + (uint32_t)(it % NSTAGE) * STAGE;
        #pragma unroll
        for (int ks = 0; ks < BK / 16; ks++) {
            const uint32_t kb = (uint32_t)(ks * 32);
            // 4 ldsm -> 8 independent MMAs
            uint32_t a0[4], a1[4], b0[4], b1[4];
            uint32_t ao = sb + a_off + kb;
            uint32_t bo = sb + b_off + kb;
            ldsm_x4(a0, ao);                 // m rows [wm*32,   +16)
            ldsm_x4(a1, ao + 16 * ROWB);     // m rows [wm*32+16, +16)
            ldsm_x4(b0, bo);                 // n cols [wn*32,   +16)
            ldsm_x4(b1, bo + 16 * ROWB);     // n cols [wn*32+16, +16)
            mma16816(d[0][0], a0, b0[0], b0[2]);
            mma16816(d[0][1], a0, b0[1], b0[3]);
            mma16816(d[0][2], a0, b1[0], b1[2]);
            mma16816(d[0][3], a0, b1[1], b1[3]);
            mma16816(d[1][0], a1, b0[0], b0[2]);
            mma16816(d[1][1], a1, b0[1], b0[3]);
            mma16816(d[1][2], a1, b1[0], b1[2]);
            mma16816(d[1][3], a1, b1[1], b1[3]);
        }
    }

    // ---- epilogue: bias + scatter ----
    #pragma unroll
    for (int m2 = 0; m2 < 2; m2++) {
        const int r0 = wm * 32 + m2 * 16 + (lane >> 2);
        const int row0 = s_rows[r0];
        const int row1 = s_rows[r0 + 8];
        #pragma unroll
        for (int n2 = 0; n2 < 4; n2++) {
            const int col = wn * 32 + n2 * 8 + (lane & 3) * 2;
            const float bx = s_bias[col], by = s_bias[col + 1];
            if (row0 >= 0) {
                float2 o = make_float2(d[m2][n2][0] + bx, d[m2][n2][1] + by);
                *reinterpret_cast<float2*>(out + (size_t)row0 * DIM_H + hbase + col) = o;
            }
            if (row1 >= 0) {
                float2 o = make_float2(d[m2][n2][2] + bx, d[m2][n2][3] + by);
                *reinterpret_cast<float2*>(out + (size_t)row1 * DIM_H + hbase + col) = o;
            }
        }
    }
}

extern "C" void kernel_launch(void* const* d_in, const int* in_sizes, int n_in,
                              void* d_out, int out_size) {
    const float* inp   = (const float*)d_in[0];
    const int*   idx32 = (const int*)d_in[1];   // int64 or int32 — detected on device
    const float* W     = (const float*)d_in[2];
    const float* bias  = (const float*)d_in[3];
    float*       out   = (float*)d_out;

    cudaFuncSetAttribute(gemm_kernel, cudaFuncAttributeMaxDynamicSharedMemorySize, GEMM_SMEM);

    prep_kernel<<<PREP_BLOCKS, 256>>>(inp, idx32, W);
    dim3 grid(DIM_H / BN, 48);   // max worklist = 2048/64 + 16 = 48
    gemm_kernel<<<grid, 128, GEMM_SMEM>>>(bias, out);
}